// round 15
// baseline (speedup 1.0000x reference)
#include <cuda_runtime.h>
#include <cuda_bf16.h>
#include <cuda_fp16.h>
#include <math.h>
#include <stdint.h>

#define NB   64
#define PP   256
#define DV   1024
#define DT   768
#define SS   512
#define NSEG 32
#define PPT  8
#define MTOT 2048          // NB*NSEG rows
#define KA   1024          // A row length (fp16)
#define KB   1024          // B row length (fp16 W^T)
#define KITER 16           // K-iterations per CTA (BK=32, half of K=1024)
#define STAGES 5

// ---------------- scratch --------------------------------------------------
static __device__ __half g_ah[MTOT * KA];              // 4 MB
static __device__ __half g_bh[DT * KB];                // 1.5 MB
static __device__ float g_part0[MTOT * DT];            // z=0: K lo half
static __device__ float g_part1[MTOT * DT];            // z=1: K hi half
static __device__ float g_pool[NB * DT];
static __device__ float g_nrm[NB * DT];
static __device__ float g_sim[NB * NB];
static __device__ int   g_rank[NB * SS];
static __device__ int   g_pos[NB * NSEG];              // inverse map: seg -> seq pos

__device__ __forceinline__ uint32_t smem_u32(const void* p) {
    uint32_t a;
    asm("{ .reg .u64 t; cvta.to.shared.u64 t, %1; cvt.u32.u64 %0, t; }" : "=r"(a) : "l"(p));
    return a;
}
__device__ __forceinline__ void cp16(uint32_t d, const void* s) {
    asm volatile("cp.async.cg.shared.global [%0], [%1], 16;" :: "r"(d), "l"(s) : "memory");
}
#define CP_COMMIT() asm volatile("cp.async.commit_group;" ::: "memory")
#define CP_WAIT3()  asm volatile("cp.async.wait_group 3;" ::: "memory")
__device__ __forceinline__ void ldsm_x4(uint32_t* r, uint32_t a) {
    asm volatile("ldmatrix.sync.aligned.m8n8.x4.shared.b16 {%0,%1,%2,%3}, [%4];"
                 : "=r"(r[0]), "=r"(r[1]), "=r"(r[2]), "=r"(r[3]) : "r"(a));
}
__device__ __forceinline__ void mma16816(float* d, const uint32_t* a, const uint32_t* b) {
    asm volatile("mma.sync.aligned.m16n8k16.row.col.f32.f16.f16.f32 "
                 "{%0,%1,%2,%3}, {%4,%5,%6,%7}, {%8,%9}, {%0,%1,%2,%3};"
                 : "+f"(d[0]), "+f"(d[1]), "+f"(d[2]), "+f"(d[3])
                 : "r"(a[0]), "r"(a[1]), "r"(a[2]), "r"(a[3]), "r"(b[0]), "r"(b[1]));
}

// ---------------- 1) LayerNorm + segment sum -> fp16 ------------------------
__global__ __launch_bounds__(256) void k_ln_segsum(const float* __restrict__ vis,
                                                   const float* __restrict__ gamma,
                                                   const float* __restrict__ beta) {
    int bs = blockIdx.x, tid = threadIdx.x;
    int lane = tid & 31, warp = tid >> 5;
    __shared__ float rs[PPT][8], rq[PPT][8], bc2[PPT][2];
    const float* base = vis + (size_t)bs * PPT * DV;
    int d0 = tid * 4;

    float4 x[PPT];
    #pragma unroll
    for (int p = 0; p < PPT; ++p)
        x[p] = *(const float4*)(base + p * DV + d0);

    #pragma unroll
    for (int p = 0; p < PPT; ++p) {
        float s = x[p].x + x[p].y + x[p].z + x[p].w;
        float q = x[p].x * x[p].x + x[p].y * x[p].y + x[p].z * x[p].z + x[p].w * x[p].w;
        #pragma unroll
        for (int o = 16; o > 0; o >>= 1) {
            s += __shfl_xor_sync(0xffffffffu, s, o);
            q += __shfl_xor_sync(0xffffffffu, q, o);
        }
        if (lane == 0) { rs[p][warp] = s; rq[p][warp] = q; }
    }
    __syncthreads();
    if (warp == 0) {
        int p = lane & 7, h = lane >> 3;
        float s2 = rs[p][h] + rs[p][h + 4];
        float q2 = rq[p][h] + rq[p][h + 4];
        s2 += __shfl_xor_sync(0xffffffffu, s2, 8);
        q2 += __shfl_xor_sync(0xffffffffu, q2, 8);
        s2 += __shfl_xor_sync(0xffffffffu, s2, 16);
        q2 += __shfl_xor_sync(0xffffffffu, q2, 16);
        if (lane < 8) {
            float mean = s2 * (1.f / DV);
            float var  = q2 * (1.f / DV) - mean * mean;
            bc2[p][0] = mean;
            bc2[p][1] = rsqrtf(var + 1e-5f);
        }
    }
    __syncthreads();

    float4 g  = *(const float4*)(gamma + d0);
    float4 be = *(const float4*)(beta  + d0);
    float a0 = 0.f, a1 = 0.f, a2 = 0.f, a3 = 0.f;
    #pragma unroll
    for (int p = 0; p < PPT; ++p) {
        float mean = bc2[p][0], rstd = bc2[p][1];
        a0 += (x[p].x - mean) * rstd * g.x + be.x;
        a1 += (x[p].y - mean) * rstd * g.y + be.y;
        a2 += (x[p].z - mean) * rstd * g.z + be.z;
        a3 += (x[p].w - mean) * rstd * g.w + be.w;
    }
    __half2 h01 = __floats2half2_rn(a0, a1);
    __half2 h23 = __floats2half2_rn(a2, a3);
    uint2 w;
    memcpy(&w.x, &h01, 4);
    memcpy(&w.y, &h23, 4);
    *(uint2*)(g_ah + (size_t)bs * KA + d0) = w;
}

// ---------------- 2a) W [1024,768] -> W^T fp16 [768,1024] -------------------
__global__ void k_wsplit(const float* __restrict__ W) {
    __shared__ float t[32][33];
    int n0 = blockIdx.x * 32, k0 = blockIdx.y * 32;
    int tx = threadIdx.x, ty = threadIdx.y;  // 32 x 8
    #pragma unroll
    for (int i = 0; i < 4; ++i)
        t[ty + 8 * i][tx] = W[(size_t)(k0 + ty + 8 * i) * DT + n0 + tx];
    __syncthreads();
    #pragma unroll
    for (int i = 0; i < 4; ++i) {
        int n = n0 + ty + 8 * i;
        g_bh[(size_t)n * KB + k0 + tx] = __float2half_rn(t[tx][ty + 8 * i]);
    }
}

// ---------------- 2c) per-row placeholder rank + inverse map ----------------
__global__ void k_rank(const int* __restrict__ ids, const int* __restrict__ phid) {
    int b = blockIdx.x, s = threadIdx.x;
    __shared__ int sc[SS];
    int ph = phid[0];
    int m = (ids[b * SS + s] == ph) ? 1 : 0;
    if (s < NSEG) g_pos[b * NSEG + s] = -1;
    sc[s] = m;
    __syncthreads();
    for (int o = 1; o < SS; o <<= 1) {
        int v = (s >= o) ? sc[s - o] : 0;
        __syncthreads();
        sc[s] += v;
        __syncthreads();
    }
    int rank = sc[s] - 1;
    int rk = (m && rank < NSEG) ? rank : -1;
    g_rank[b * SS + s] = rk;
    if (rk >= 0) g_pos[b * NSEG + rk] = s;
}

// ---------------- 2b) mma.sync fp16 GEMM, split-K=2, 192 CTAs ---------------
#define ABYTES (128 * 80)
#define BBYTES (96 * 80)
#define STGB   (ABYTES + BBYTES)
__global__ __launch_bounds__(256, 2) void k_gemm_mma() {
    extern __shared__ __align__(16) char sm[];
    uint32_t smb = smem_u32(sm);
    int tid = threadIdx.x, lane = tid & 31, wid = tid >> 5;
    int wm = wid & 3, wn = wid >> 2;
    int m0 = blockIdx.y * 128, n0 = blockIdx.x * 96;
    int z = blockIdx.z;
    int koff = z * 512;

    const __half* gA = g_ah + (size_t)m0 * KA + koff;
    const __half* gB = g_bh + (size_t)n0 * KB + koff;

    auto prefetch = [&](int i, int stg) {
        int kin = i << 5;
        uint32_t stA = smb + stg * STGB;
        uint32_t stB = stA + ABYTES;
        #pragma unroll
        for (int j = 0; j < 2; ++j) {
            int ca = tid + j * 256;
            int r = ca >> 2, c = ca & 3;
            cp16(stA + r * 80 + c * 16, gA + (size_t)r * KA + kin + c * 8);
        }
        {
            int r = tid >> 2, c = tid & 3;
            cp16(stB + r * 80 + c * 16, gB + (size_t)r * KB + kin + c * 8);
        }
        if (tid < 128) {
            int cb = tid + 256;
            int r = cb >> 2, c = cb & 3;
            cp16(stB + r * 80 + c * 16, gB + (size_t)r * KB + kin + c * 8);
        }
        CP_COMMIT();
    };

    float d[2][6][4];
    #pragma unroll
    for (int i = 0; i < 2; ++i)
        #pragma unroll
        for (int j = 0; j < 6; ++j)
            #pragma unroll
            for (int c = 0; c < 4; ++c) d[i][j][c] = 0.f;

    #pragma unroll
    for (int s = 0; s < STAGES - 1; ++s) prefetch(s, s);   // 4 pending

    int aRow = (wm * 32 + (lane & 15)) * 80 + (lane >> 4) * 16;
    int bRow = (wn * 48 + (lane & 7) + ((lane >> 4) << 3)) * 80 + ((lane >> 3) & 1) * 16;

    int stg = 0, pstg = STAGES - 1;
    for (int i = 0; i < KITER; ++i) {
        CP_WAIT3();
        __syncthreads();
        if (i + STAGES - 1 < KITER) {
            prefetch(i + STAGES - 1, pstg);
            if (++pstg == STAGES) pstg = 0;
        } else CP_COMMIT();
        uint32_t stA = smb + stg * STGB;
        uint32_t stB = stA + ABYTES;
        if (++stg == STAGES) stg = 0;
        #pragma unroll
        for (int s = 0; s < 2; ++s) {
            uint32_t a[2][4], b[3][4];
            #pragma unroll
            for (int mf = 0; mf < 2; ++mf)
                ldsm_x4(a[mf], stA + aRow + mf * 16 * 80 + s * 32);
            #pragma unroll
            for (int np = 0; np < 3; ++np)
                ldsm_x4(b[np], stB + bRow + np * 16 * 80 + s * 32);
            #pragma unroll
            for (int mf = 0; mf < 2; ++mf)
                #pragma unroll
                for (int nf = 0; nf < 6; ++nf)
                    mma16816(d[mf][nf], a[mf], &b[nf >> 1][(nf & 1) * 2]);
        }
    }

    float* outb = z ? g_part1 : g_part0;
    int grp = lane >> 2, tig = lane & 3;
    #pragma unroll
    for (int nf = 0; nf < 6; ++nf) {
        int n = n0 + wn * 48 + nf * 8 + tig * 2;
        #pragma unroll
        for (int mf = 0; mf < 2; ++mf) {
            int m = m0 + wm * 32 + mf * 16 + grp;
            *(float2*)(outb + (size_t)m * DT + n)       = make_float2(d[mf][nf][0], d[mf][nf][1]);
            *(float2*)(outb + (size_t)(m + 8) * DT + n) = make_float2(d[mf][nf][2], d[mf][nf][3]);
        }
    }
}

// ---------------- 3) combine halves + bias -> scatter to out; pooled --------
__global__ __launch_bounds__(256) void k_combine(const float* __restrict__ bproj,
                                                 float* __restrict__ out) {
    int b = blockIdx.y, tid = threadIdx.x;
    int d = blockIdx.x * 128 + (tid & 127);
    int sg0 = tid >> 7;
    __shared__ float sp[256];
    float bias = bproj[d];
    size_t base = (size_t)b * NSEG * DT + d;
    float acc = 0.f;
    #pragma unroll
    for (int sg = sg0; sg < NSEG; sg += 2) {
        size_t idx = base + (size_t)sg * DT;
        float s = g_part0[idx] + g_part1[idx];
        acc += s;
        int pos = g_pos[b * NSEG + sg];
        if (pos >= 0)
            out[((size_t)b * SS + pos) * DT + d] = s * 0.125f + bias;
    }
    sp[tid] = acc;
    __syncthreads();
    if (tid < 128)
        g_pool[(size_t)b * DT + d] = (sp[tid] + sp[tid + 128]) * (0.125f / 32.f) + bias;
}

// ---------------- 4) L2 normalize pooled ------------------------------------
__global__ __launch_bounds__(768) void k_norm() {
    int b = blockIdx.x, tid = threadIdx.x;
    int lane = tid & 31, warp = tid >> 5;
    __shared__ float red[24];
    __shared__ float bn;
    float p = g_pool[(size_t)b * DT + tid];
    float q = p * p;
    #pragma unroll
    for (int o = 16; o > 0; o >>= 1) q += __shfl_xor_sync(0xffffffffu, q, o);
    if (lane == 0) red[warp] = q;
    __syncthreads();
    if (warp == 0) {
        float q2 = lane < 24 ? red[lane] : 0.f;
        #pragma unroll
        for (int o = 16; o > 0; o >>= 1) q2 += __shfl_xor_sync(0xffffffffu, q2, o);
        if (lane == 0) bn = 1.f / sqrtf(q2);
    }
    __syncthreads();
    g_nrm[(size_t)b * DT + tid] = p * bn;
}

// ---------------- 5) sim = (nrm @ nrm^T) / TEMP -----------------------------
__global__ void k_sim() {
    int i = blockIdx.y, jq = blockIdx.x;
    int tid = threadIdx.x, w = tid >> 5, lane = tid & 31;
    __shared__ float ni[DT];
    if (tid < 192)
        *(float4*)(ni + tid * 4) = *(const float4*)(g_nrm + (size_t)i * DT + tid * 4);
    __syncthreads();
    #pragma unroll
    for (int jj = 0; jj < 2; ++jj) {
        int j = jq * 16 + w * 2 + jj;
        const float4* nj = (const float4*)(g_nrm + (size_t)j * DT);
        float s = 0.f;
        #pragma unroll
        for (int it = 0; it < 6; ++it) {
            int d4 = lane + it * 32;
            float4 bb = nj[d4];
            float4 aa = *(const float4*)(ni + d4 * 4);
            s += aa.x * bb.x + aa.y * bb.y + aa.z * bb.z + aa.w * bb.w;
        }
        #pragma unroll
        for (int o = 16; o > 0; o >>= 1) s += __shfl_xor_sync(0xffffffffu, s, o);
        if (lane == 0) g_sim[i * NB + j] = s / 0.07f;
    }
}

// ---------------- 6) symmetric InfoNCE loss ---------------------------------
__global__ void k_loss(float* __restrict__ out) {
    int i = threadIdx.x;
    __shared__ float red[64];
    float diag = g_sim[i * NB + i];
    float m = -1e30f;
    for (int j = 0; j < NB; ++j) m = fmaxf(m, g_sim[i * NB + j]);
    float se = 0.f;
    for (int j = 0; j < NB; ++j) se += expf(g_sim[i * NB + j] - m);
    float rl = (m + logf(se)) - diag;
    float mc = -1e30f;
    for (int j = 0; j < NB; ++j) mc = fmaxf(mc, g_sim[j * NB + i]);
    float sc = 0.f;
    for (int j = 0; j < NB; ++j) sc += expf(g_sim[j * NB + i] - mc);
    float cl = (mc + logf(sc)) - diag;
    red[i] = rl + cl;
    __syncthreads();
    #pragma unroll
    for (int o = 32; o > 0; o >>= 1) {
        if (i < o) red[i] += red[i + o];
        __syncthreads();
    }
    if (i == 0) out[0] = red[0] * (0.5f / NB);
}

// ---------------- 7) text_emb: non-placeholder rows, high-MLP ---------------
#define TROWS 16
__global__ __launch_bounds__(384) void k_text_nonph(const float* __restrict__ wte,
                                                    const int* __restrict__ ids,
                                                    float* __restrict__ out) {
    int tid = threadIdx.x;
    int c    = tid % 192;            // float4 index within row
    int half = tid / 192;            // 0 or 1
    int base = blockIdx.x * 32 + half * TROWS;

    int rk[TROWS], id[TROWS];
    #pragma unroll
    for (int i = 0; i < TROWS; ++i) {
        rk[i] = g_rank[base + i];
        id[i] = __ldg(ids + base + i);
    }
    #pragma unroll 4
    for (int i = 0; i < TROWS; ++i) {
        if (rk[i] < 0) {
            float4 v = *((const float4*)(wte + (size_t)id[i] * DT) + c);
            *((float4*)out + (size_t)(base + i) * (DT / 4) + c) = v;
        }
    }
}

// ---------------- streams/events (created at static init; not device mem) ---
static cudaStream_t g_s1, g_s2;
static cudaEvent_t  g_evF, g_evR, g_evT, g_evA;
namespace {
struct StreamInit {
    StreamInit() {
        int lo = 0, hi = 0;
        cudaDeviceGetStreamPriorityRange(&lo, &hi);
        cudaStreamCreateWithPriority(&g_s1, cudaStreamNonBlocking, hi);
        cudaStreamCreateWithPriority(&g_s2, cudaStreamNonBlocking, lo);
        cudaEventCreateWithFlags(&g_evF, cudaEventDisableTiming);
        cudaEventCreateWithFlags(&g_evR, cudaEventDisableTiming);
        cudaEventCreateWithFlags(&g_evT, cudaEventDisableTiming);
        cudaEventCreateWithFlags(&g_evA, cudaEventDisableTiming);
    }
} g_streaminit;
}

// ---------------- launch ----------------------------------------------------
// A-chain (g_s1): wsplit -> ln -> gemm -> combine -> norm -> sim -> loss
// B-chain (g_s2): rank -> text        (independent; overlaps the A-chain)
// Origin stream only forks (evF) and joins (evA + evT) — no legacy-stream
// kernel launches between fork and join, so no implicit serialization.
extern "C" void kernel_launch(void* const* d_in, const int* in_sizes, int n_in,
                              void* d_out, int out_size) {
    const float* vis   = (const float*)d_in[0];
    const float* gamma = (const float*)d_in[1];
    const float* beta  = (const float*)d_in[2];
    const float* W     = (const float*)d_in[3];
    const float* bproj = (const float*)d_in[4];
    const float* wte   = (const float*)d_in[5];
    const int*   ids   = (const int*)d_in[6];
    const int*   phid  = (const int*)d_in[7];
    float* out = (float*)d_out;

    cudaFuncSetAttribute(k_gemm_mma, cudaFuncAttributeMaxDynamicSharedMemorySize,
                         STAGES * STGB);

    // fork both side streams from the origin stream
    cudaEventRecord(g_evF, 0);
    cudaStreamWaitEvent(g_s1, g_evF, 0);
    cudaStreamWaitEvent(g_s2, g_evF, 0);

    k_wsplit<<<dim3(DT / 32, DV / 32), dim3(32, 8), 0, g_s1>>>(W);     // call 1 (A)
    k_rank<<<NB, SS, 0, g_s2>>>(ids, phid);                            // call 2 (B)
    cudaEventRecord(g_evR, g_s2);
    k_ln_segsum<<<NB * NSEG, 256, 0, g_s1>>>(vis, gamma, beta);        // call 3 (A)
    k_text_nonph<<<NB * SS / 32, 384, 0, g_s2>>>(wte, ids, out);       // call 4 (B, profiled)
    cudaEventRecord(g_evT, g_s2);

    k_gemm_mma<<<dim3(DT / 96, MTOT / 128, 2), 256, STAGES * STGB, g_s1>>>(); // call 5 (A)

    cudaStreamWaitEvent(g_s1, g_evR, 0);
    k_combine<<<dim3(6, NB), 256, 0, g_s1>>>(bproj, out);              // call 6 (A)
    k_norm<<<NB, 768, 0, g_s1>>>();                                    // call 7 (A)
    k_sim<<<dim3(4, NB), 256, 0, g_s1>>>();                            // call 8 (A)
    k_loss<<<1, 64, 0, g_s1>>>(out + (size_t)out_size - 1);            // call 9 (A)
    cudaEventRecord(g_evA, g_s1);

    // rejoin both side streams on the origin stream (capture requirement)
    cudaStreamWaitEvent(0, g_evA, 0);
    cudaStreamWaitEvent(0, g_evT, 0);
}

// round 16
// speedup vs baseline: 1.1529x; 1.1529x over previous
#include <cuda_runtime.h>
#include <cuda_bf16.h>
#include <cuda_fp16.h>
#include <math.h>
#include <stdint.h>

#define NB   64
#define PP   256
#define DV   1024
#define DT   768
#define SS   512
#define NSEG 32
#define PPT  8
#define MTOT 2048          // NB*NSEG rows
#define KA   1024          // A row length (fp16)
#define KB   1024          // B row length (fp16 W^T)
#define KITER 16           // K-iterations per CTA (BK=32, half of K=1024)
#define STAGES 5

// ---------------- scratch --------------------------------------------------
static __device__ __half g_ah[MTOT * KA];              // 4 MB
static __device__ __half g_bh[DT * KB];                // 1.5 MB
static __device__ float g_part0[MTOT * DT];            // z=0: K lo half
static __device__ float g_part1[MTOT * DT];            // z=1: K hi half
static __device__ float g_pool[NB * DT];               // unnormalized pooled means
static __device__ float g_sim[NB * NB];
static __device__ int   g_rank[NB * SS];
static __device__ int   g_pos[NB * NSEG];              // inverse map: seg -> seq pos

__device__ __forceinline__ uint32_t smem_u32(const void* p) {
    uint32_t a;
    asm("{ .reg .u64 t; cvta.to.shared.u64 t, %1; cvt.u32.u64 %0, t; }" : "=r"(a) : "l"(p));
    return a;
}
__device__ __forceinline__ void cp16(uint32_t d, const void* s) {
    asm volatile("cp.async.cg.shared.global [%0], [%1], 16;" :: "r"(d), "l"(s) : "memory");
}
#define CP_COMMIT() asm volatile("cp.async.commit_group;" ::: "memory")
#define CP_WAIT3()  asm volatile("cp.async.wait_group 3;" ::: "memory")
__device__ __forceinline__ void ldsm_x4(uint32_t* r, uint32_t a) {
    asm volatile("ldmatrix.sync.aligned.m8n8.x4.shared.b16 {%0,%1,%2,%3}, [%4];"
                 : "=r"(r[0]), "=r"(r[1]), "=r"(r[2]), "=r"(r[3]) : "r"(a));
}
__device__ __forceinline__ void mma16816(float* d, const uint32_t* a, const uint32_t* b) {
    asm volatile("mma.sync.aligned.m16n8k16.row.col.f32.f16.f16.f32 "
                 "{%0,%1,%2,%3}, {%4,%5,%6,%7}, {%8,%9}, {%0,%1,%2,%3};"
                 : "+f"(d[0]), "+f"(d[1]), "+f"(d[2]), "+f"(d[3])
                 : "r"(a[0]), "r"(a[1]), "r"(a[2]), "r"(a[3]), "r"(b[0]), "r"(b[1]));
}

// ---------------- 1) LayerNorm + segment sum -> fp16 ------------------------
__global__ __launch_bounds__(256) void k_ln_segsum(const float* __restrict__ vis,
                                                   const float* __restrict__ gamma,
                                                   const float* __restrict__ beta) {
    int bs = blockIdx.x, tid = threadIdx.x;
    int lane = tid & 31, warp = tid >> 5;
    __shared__ float rs[PPT][8], rq[PPT][8], bc2[PPT][2];
    const float* base = vis + (size_t)bs * PPT * DV;
    int d0 = tid * 4;

    float4 x[PPT];
    #pragma unroll
    for (int p = 0; p < PPT; ++p)
        x[p] = *(const float4*)(base + p * DV + d0);

    #pragma unroll
    for (int p = 0; p < PPT; ++p) {
        float s = x[p].x + x[p].y + x[p].z + x[p].w;
        float q = x[p].x * x[p].x + x[p].y * x[p].y + x[p].z * x[p].z + x[p].w * x[p].w;
        #pragma unroll
        for (int o = 16; o > 0; o >>= 1) {
            s += __shfl_xor_sync(0xffffffffu, s, o);
            q += __shfl_xor_sync(0xffffffffu, q, o);
        }
        if (lane == 0) { rs[p][warp] = s; rq[p][warp] = q; }
    }
    __syncthreads();
    if (warp == 0) {
        int p = lane & 7, h = lane >> 3;
        float s2 = rs[p][h] + rs[p][h + 4];
        float q2 = rq[p][h] + rq[p][h + 4];
        s2 += __shfl_xor_sync(0xffffffffu, s2, 8);
        q2 += __shfl_xor_sync(0xffffffffu, q2, 8);
        s2 += __shfl_xor_sync(0xffffffffu, s2, 16);
        q2 += __shfl_xor_sync(0xffffffffu, q2, 16);
        if (lane < 8) {
            float mean = s2 * (1.f / DV);
            float var  = q2 * (1.f / DV) - mean * mean;
            bc2[p][0] = mean;
            bc2[p][1] = rsqrtf(var + 1e-5f);
        }
    }
    __syncthreads();

    float4 g  = *(const float4*)(gamma + d0);
    float4 be = *(const float4*)(beta  + d0);
    float a0 = 0.f, a1 = 0.f, a2 = 0.f, a3 = 0.f;
    #pragma unroll
    for (int p = 0; p < PPT; ++p) {
        float mean = bc2[p][0], rstd = bc2[p][1];
        a0 += (x[p].x - mean) * rstd * g.x + be.x;
        a1 += (x[p].y - mean) * rstd * g.y + be.y;
        a2 += (x[p].z - mean) * rstd * g.z + be.z;
        a3 += (x[p].w - mean) * rstd * g.w + be.w;
    }
    __half2 h01 = __floats2half2_rn(a0, a1);
    __half2 h23 = __floats2half2_rn(a2, a3);
    uint2 w;
    memcpy(&w.x, &h01, 4);
    memcpy(&w.y, &h23, 4);
    *(uint2*)(g_ah + (size_t)bs * KA + d0) = w;
}

// ---------------- 2) prep: W^T fp16 transpose + placeholder rank ------------
// 832 blocks x 512 thr. blocks [0,768): wsplit tiles; [768,832): rank rows.
__global__ __launch_bounds__(512) void k_prep(const float* __restrict__ W,
                                              const int* __restrict__ ids,
                                              const int* __restrict__ phid) {
    __shared__ __align__(16) char shm[32 * 33 * 4];
    int bx = blockIdx.x, tid = threadIdx.x;
    if (bx < 768) {
        float (*t)[33] = (float(*)[33])shm;
        int n0 = (bx % 24) * 32, k0 = (bx / 24) * 32;
        int tx = tid & 31, ty = tid >> 5;          // ty in 0..15; use 0..7
        if (tid < 256) {
            #pragma unroll
            for (int i = 0; i < 4; ++i)
                t[ty + 8 * i][tx] = W[(size_t)(k0 + ty + 8 * i) * DT + n0 + tx];
        }
        __syncthreads();
        if (tid < 256) {
            #pragma unroll
            for (int i = 0; i < 4; ++i) {
                int n = n0 + ty + 8 * i;
                g_bh[(size_t)n * KB + k0 + tx] = __float2half_rn(t[tx][ty + 8 * i]);
            }
        }
    } else {
        int* sc = (int*)shm;
        int b = bx - 768, s = tid;
        int ph = phid[0];
        int m = (ids[b * SS + s] == ph) ? 1 : 0;
        if (s < NSEG) g_pos[b * NSEG + s] = -1;
        sc[s] = m;
        __syncthreads();
        for (int o = 1; o < SS; o <<= 1) {
            int v = (s >= o) ? sc[s - o] : 0;
            __syncthreads();
            sc[s] += v;
            __syncthreads();
        }
        int rank = sc[s] - 1;
        int rk = (m && rank < NSEG) ? rank : -1;
        g_rank[b * SS + s] = rk;
        if (rk >= 0) g_pos[b * NSEG + rk] = s;
    }
}

// ---------------- 3) mma.sync fp16 GEMM, split-K=2, 192 CTAs ----------------
#define ABYTES (128 * 80)
#define BBYTES (96 * 80)
#define STGB   (ABYTES + BBYTES)
__global__ __launch_bounds__(256, 2) void k_gemm_mma() {
    extern __shared__ __align__(16) char sm[];
    uint32_t smb = smem_u32(sm);
    int tid = threadIdx.x, lane = tid & 31, wid = tid >> 5;
    int wm = wid & 3, wn = wid >> 2;
    int m0 = blockIdx.y * 128, n0 = blockIdx.x * 96;
    int z = blockIdx.z;
    int koff = z * 512;

    const __half* gA = g_ah + (size_t)m0 * KA + koff;
    const __half* gB = g_bh + (size_t)n0 * KB + koff;

    auto prefetch = [&](int i, int stg) {
        int kin = i << 5;
        uint32_t stA = smb + stg * STGB;
        uint32_t stB = stA + ABYTES;
        #pragma unroll
        for (int j = 0; j < 2; ++j) {
            int ca = tid + j * 256;
            int r = ca >> 2, c = ca & 3;
            cp16(stA + r * 80 + c * 16, gA + (size_t)r * KA + kin + c * 8);
        }
        {
            int r = tid >> 2, c = tid & 3;
            cp16(stB + r * 80 + c * 16, gB + (size_t)r * KB + kin + c * 8);
        }
        if (tid < 128) {
            int cb = tid + 256;
            int r = cb >> 2, c = cb & 3;
            cp16(stB + r * 80 + c * 16, gB + (size_t)r * KB + kin + c * 8);
        }
        CP_COMMIT();
    };

    float d[2][6][4];
    #pragma unroll
    for (int i = 0; i < 2; ++i)
        #pragma unroll
        for (int j = 0; j < 6; ++j)
            #pragma unroll
            for (int c = 0; c < 4; ++c) d[i][j][c] = 0.f;

    #pragma unroll
    for (int s = 0; s < STAGES - 1; ++s) prefetch(s, s);   // 4 pending

    int aRow = (wm * 32 + (lane & 15)) * 80 + (lane >> 4) * 16;
    int bRow = (wn * 48 + (lane & 7) + ((lane >> 4) << 3)) * 80 + ((lane >> 3) & 1) * 16;

    int stg = 0, pstg = STAGES - 1;
    for (int i = 0; i < KITER; ++i) {
        CP_WAIT3();
        __syncthreads();
        if (i + STAGES - 1 < KITER) {
            prefetch(i + STAGES - 1, pstg);
            if (++pstg == STAGES) pstg = 0;
        } else CP_COMMIT();
        uint32_t stA = smb + stg * STGB;
        uint32_t stB = stA + ABYTES;
        if (++stg == STAGES) stg = 0;
        #pragma unroll
        for (int s = 0; s < 2; ++s) {
            uint32_t a[2][4], b[3][4];
            #pragma unroll
            for (int mf = 0; mf < 2; ++mf)
                ldsm_x4(a[mf], stA + aRow + mf * 16 * 80 + s * 32);
            #pragma unroll
            for (int np = 0; np < 3; ++np)
                ldsm_x4(b[np], stB + bRow + np * 16 * 80 + s * 32);
            #pragma unroll
            for (int mf = 0; mf < 2; ++mf)
                #pragma unroll
                for (int nf = 0; nf < 6; ++nf)
                    mma16816(d[mf][nf], a[mf], &b[nf >> 1][(nf & 1) * 2]);
        }
    }

    float* outb = z ? g_part1 : g_part0;
    int grp = lane >> 2, tig = lane & 3;
    #pragma unroll
    for (int nf = 0; nf < 6; ++nf) {
        int n = n0 + wn * 48 + nf * 8 + tig * 2;
        #pragma unroll
        for (int mf = 0; mf < 2; ++mf) {
            int m = m0 + wm * 32 + mf * 16 + grp;
            *(float2*)(outb + (size_t)m * DT + n)       = make_float2(d[mf][nf][0], d[mf][nf][1]);
            *(float2*)(outb + (size_t)(m + 8) * DT + n) = make_float2(d[mf][nf][2], d[mf][nf][3]);
        }
    }
}

// ---------------- 4) text_emb: branchless gather, batch-4 loads -------------
// 1024 blocks x 384 thr. Loads unconditional (ph positions map to the valid
// wte row V-1), stores predicated on rank<0. 4 LDG.128 in flight per step.
#define TROWS 16
__global__ __launch_bounds__(384) void k_text_nonph(const float* __restrict__ wte,
                                                    const int* __restrict__ ids,
                                                    float* __restrict__ out) {
    int tid = threadIdx.x;
    int c    = tid % 192;
    int half = tid / 192;
    int base = blockIdx.x * 32 + half * TROWS;

    int rk[TROWS], id[TROWS];
    #pragma unroll
    for (int i = 0; i < TROWS; ++i) {
        rk[i] = g_rank[base + i];
        id[i] = __ldg(ids + base + i);
    }
    #pragma unroll
    for (int i0 = 0; i0 < TROWS; i0 += 4) {
        float4 v0 = ((const float4*)(wte + (size_t)id[i0 + 0] * DT))[c];
        float4 v1 = ((const float4*)(wte + (size_t)id[i0 + 1] * DT))[c];
        float4 v2 = ((const float4*)(wte + (size_t)id[i0 + 2] * DT))[c];
        float4 v3 = ((const float4*)(wte + (size_t)id[i0 + 3] * DT))[c];
        if (rk[i0 + 0] < 0) ((float4*)out)[(size_t)(base + i0 + 0) * 192 + c] = v0;
        if (rk[i0 + 1] < 0) ((float4*)out)[(size_t)(base + i0 + 1) * 192 + c] = v1;
        if (rk[i0 + 2] < 0) ((float4*)out)[(size_t)(base + i0 + 2) * 192 + c] = v2;
        if (rk[i0 + 3] < 0) ((float4*)out)[(size_t)(base + i0 + 3) * 192 + c] = v3;
    }
}

// ---------------- 5) combine halves + bias -> scatter to out; pooled --------
__global__ __launch_bounds__(256) void k_combine(const float* __restrict__ bproj,
                                                 float* __restrict__ out) {
    int b = blockIdx.y, tid = threadIdx.x;
    int d = blockIdx.x * 128 + (tid & 127);
    int sg0 = tid >> 7;
    __shared__ float sp[256];
    float bias = bproj[d];
    size_t base = (size_t)b * NSEG * DT + d;
    float acc = 0.f;
    #pragma unroll
    for (int sg = sg0; sg < NSEG; sg += 2) {
        size_t idx = base + (size_t)sg * DT;
        float s = g_part0[idx] + g_part1[idx];
        acc += s;
        int pos = g_pos[b * NSEG + sg];
        if (pos >= 0)
            out[((size_t)b * SS + pos) * DT + d] = s * 0.125f + bias;
    }
    sp[tid] = acc;
    __syncthreads();
    if (tid < 128)
        g_pool[(size_t)b * DT + d] = (sp[tid] + sp[tid + 128]) * (0.125f / 32.f) + bias;
}

// ---------------- 6) sim = cos-sim / TEMP (norm fused, no k_norm) -----------
__global__ __launch_bounds__(256) void k_sim() {
    int i = blockIdx.y, jq = blockIdx.x;
    int tid = threadIdx.x, w = tid >> 5, lane = tid & 31;
    __shared__ float ni[DT];
    __shared__ float red[8];
    __shared__ float qi_s;
    if (tid < 192)
        *(float4*)(ni + tid * 4) = *(const float4*)(g_pool + (size_t)i * DT + tid * 4);
    __syncthreads();
    // qi = |pool_i|^2 (block reduce; 3 elems per thread)
    {
        float q = ni[tid] * ni[tid] + ni[tid + 256] * ni[tid + 256]
                + ni[tid + 512] * ni[tid + 512];
        #pragma unroll
        for (int o = 16; o > 0; o >>= 1) q += __shfl_xor_sync(0xffffffffu, q, o);
        if (lane == 0) red[w] = q;
        __syncthreads();
        if (tid == 0) {
            float s = 0.f;
            #pragma unroll
            for (int k = 0; k < 8; ++k) s += red[k];
            qi_s = s;
        }
        __syncthreads();
    }
    float qi = qi_s;
    #pragma unroll
    for (int jj = 0; jj < 2; ++jj) {
        int j = jq * 16 + w * 2 + jj;
        const float4* nj = (const float4*)(g_pool + (size_t)j * DT);
        float s = 0.f, qj = 0.f;
        #pragma unroll
        for (int it = 0; it < 6; ++it) {
            int d4 = lane + it * 32;
            float4 bb = nj[d4];
            float4 aa = *(const float4*)(ni + d4 * 4);
            s  += aa.x * bb.x + aa.y * bb.y + aa.z * bb.z + aa.w * bb.w;
            qj += bb.x * bb.x + bb.y * bb.y + bb.z * bb.z + bb.w * bb.w;
        }
        #pragma unroll
        for (int o = 16; o > 0; o >>= 1) {
            s  += __shfl_xor_sync(0xffffffffu, s, o);
            qj += __shfl_xor_sync(0xffffffffu, qj, o);
        }
        if (lane == 0)
            g_sim[i * NB + j] = s * rsqrtf(qi * qj) * (1.f / 0.07f);
    }
}

// ---------------- 7) symmetric InfoNCE loss ---------------------------------
__global__ void k_loss(float* __restrict__ out) {
    int i = threadIdx.x;
    __shared__ float red[64];
    float diag = g_sim[i * NB + i];
    float m = -1e30f;
    for (int j = 0; j < NB; ++j) m = fmaxf(m, g_sim[i * NB + j]);
    float se = 0.f;
    for (int j = 0; j < NB; ++j) se += expf(g_sim[i * NB + j] - m);
    float rl = (m + logf(se)) - diag;
    float mc = -1e30f;
    for (int j = 0; j < NB; ++j) mc = fmaxf(mc, g_sim[j * NB + i]);
    float sc = 0.f;
    for (int j = 0; j < NB; ++j) sc += expf(g_sim[j * NB + i] - mc);
    float cl = (mc + logf(sc)) - diag;
    red[i] = rl + cl;
    __syncthreads();
    #pragma unroll
    for (int o = 32; o > 0; o >>= 1) {
        if (i < o) red[i] += red[i + o];
        __syncthreads();
    }
    if (i == 0) out[0] = red[0] * (0.5f / NB);
}

// ---------------- streams/events (created at static init; not device mem) ---
static cudaStream_t g_s1, g_s2;
static cudaEvent_t  g_evF, g_evP, g_evT, g_evA;
namespace {
struct StreamInit {
    StreamInit() {
        int lo = 0, hi = 0;
        cudaDeviceGetStreamPriorityRange(&lo, &hi);
        cudaStreamCreateWithPriority(&g_s1, cudaStreamNonBlocking, hi);
        cudaStreamCreateWithPriority(&g_s2, cudaStreamNonBlocking, lo);
        cudaEventCreateWithFlags(&g_evF, cudaEventDisableTiming);
        cudaEventCreateWithFlags(&g_evP, cudaEventDisableTiming);
        cudaEventCreateWithFlags(&g_evT, cudaEventDisableTiming);
        cudaEventCreateWithFlags(&g_evA, cudaEventDisableTiming);
    }
} g_streaminit;
}

// ---------------- launch ----------------------------------------------------
// A-chain (g_s1): ln -> gemm(waits prep) -> combine -> sim -> loss
// B-chain (g_s2): prep(wsplit+rank) -> text
extern "C" void kernel_launch(void* const* d_in, const int* in_sizes, int n_in,
                              void* d_out, int out_size) {
    const float* vis   = (const float*)d_in[0];
    const float* gamma = (const float*)d_in[1];
    const float* beta  = (const float*)d_in[2];
    const float* W     = (const float*)d_in[3];
    const float* bproj = (const float*)d_in[4];
    const float* wte   = (const float*)d_in[5];
    const int*   ids   = (const int*)d_in[6];
    const int*   phid  = (const int*)d_in[7];
    float* out = (float*)d_out;

    cudaFuncSetAttribute(k_gemm_mma, cudaFuncAttributeMaxDynamicSharedMemorySize,
                         STAGES * STGB);

    cudaEventRecord(g_evF, 0);
    cudaStreamWaitEvent(g_s1, g_evF, 0);
    cudaStreamWaitEvent(g_s2, g_evF, 0);

    k_ln_segsum<<<NB * NSEG, 256, 0, g_s1>>>(vis, gamma, beta);        // call 1 (A)
    k_prep<<<832, 512, 0, g_s2>>>(W, ids, phid);                       // call 2 (B)
    cudaEventRecord(g_evP, g_s2);

    cudaStreamWaitEvent(g_s1, g_evP, 0);
    k_gemm_mma<<<dim3(DT / 96, MTOT / 128, 2), 256, STAGES * STGB, g_s1>>>(); // call 3 (A)
    k_text_nonph<<<NB * SS / 32, 384, 0, g_s2>>>(wte, ids, out);       // call 4 (B, profiled)
    cudaEventRecord(g_evT, g_s2);

    k_combine<<<dim3(6, NB), 256, 0, g_s1>>>(bproj, out);              // call 5 (A)
    k_sim<<<dim3(4, NB), 256, 0, g_s1>>>();                            // call 6 (A)
    k_loss<<<1, 64, 0, g_s1>>>(out + (size_t)out_size - 1);            // call 7 (A)
    cudaEventRecord(g_evA, g_s1);

    cudaStreamWaitEvent(0, g_evA, 0);
    cudaStreamWaitEvent(0, g_evT, 0);
}